// round 1
// baseline (speedup 1.0000x reference)
#include <cuda_runtime.h>
#include <stdint.h>

#define SLEN 400000
#define WIN  400
#define NW   1000      // SLEN / WIN
#define NA   3
#define NR   64
#define NB   2
#define KTOP 8
#define NF4  100       // WIN / 4

__device__ __forceinline__ float warp_sum(float v) {
#pragma unroll
    for (int o = 16; o; o >>= 1) v += __shfl_xor_sync(0xffffffffu, v, o);
    return v;
}

__device__ __forceinline__ unsigned long long mk_key(float v, int r) {
    unsigned u = __float_as_uint(v);
    u = (u & 0x80000000u) ? ~u : (u | 0x80000000u);   // order-preserving map
    return (((unsigned long long)u) << 6) | (unsigned long long)(63 - r);
}

__global__ __launch_bounds__(256, 6)
void fused_windowed_topk(const float* __restrict__ mixed,
                         const float* __restrict__ ref,
                         const float* __restrict__ weights,
                         float* __restrict__ out,
                         int out_size) {
    __shared__ float s_scores[NB][NR];

    const int w    = blockIdx.x;      // window
    const int a    = blockIdx.y;      // ancestry
    const int tid  = threadIdx.x;
    const int warp = tid >> 5;
    const int lane = tid & 31;

    // ---- preload both mixed windows into registers (float4, coalesced) ----
    const float4* m0p = (const float4*)(mixed + 0 * SLEN + w * WIN);
    const float4* m1p = (const float4*)(mixed + 1 * SLEN + w * WIN);
    float4 m0[4], m1[4];
#pragma unroll
    for (int t = 0; t < 4; t++) {
        int j4 = lane + 32 * t;
        if (j4 < NF4) {
            m0[t] = __ldg(m0p + j4);
            m1[t] = __ldg(m1p + j4);
        } else {
            m0[t] = make_float4(0.f, 0.f, 0.f, 0.f);
            m1[t] = make_float4(0.f, 0.f, 0.f, 0.f);
        }
    }

    // ---- stream ref rows: warp handles 8 refs, dual dot-products ----
#pragma unroll
    for (int rr = 0; rr < 8; rr++) {
        int r = warp * 8 + rr;
        const float4* rp =
            (const float4*)(ref + (size_t)(a * NR + r) * SLEN + (size_t)w * WIN);
        float s0 = 0.f, s1 = 0.f;
#pragma unroll
        for (int t = 0; t < 4; t++) {
            int j4 = lane + 32 * t;
            if (j4 < NF4) {
                float4 rv = __ldg(rp + j4);
                s0 += rv.x * m0[t].x + rv.y * m0[t].y + rv.z * m0[t].z + rv.w * m0[t].w;
                s1 += rv.x * m1[t].x + rv.y * m1[t].y + rv.z * m1[t].z + rv.w * m1[t].w;
            }
        }
        s0 = warp_sum(s0);
        s1 = warp_sum(s1);
        if (lane == 0) {
            s_scores[0][r] = s0 * (1.0f / WIN);
            s_scores[1][r] = s1 * (1.0f / WIN);
        }
    }
    __syncthreads();

    // ---- top-k with JAX tie-breaking: warps 0/1 handle b = 0/1 ----
    if (warp < NB) {
        const int b = warp;

        float wts[KTOP];
#pragma unroll
        for (int k = 0; k < KTOP; k++) wts[k] = __ldg(weights + k);

        float v0 = s_scores[b][lane];
        float v1 = s_scores[b][lane + 32];
        unsigned long long k0 = mk_key(v0, lane);
        unsigned long long k1 = mk_key(v1, lane + 32);

        const int  base      = (b * NA + a) * NW + w;
        const int  need_full = NB * NA * NW * (1 + KTOP);   // 54000
        const bool write_idx = (out_size >= need_full);

        float acc = 0.f;
#pragma unroll
        for (int k = 0; k < KTOP; k++) {
            unsigned long long km = (k0 > k1) ? k0 : k1;
#pragma unroll
            for (int o = 16; o; o >>= 1) {
                unsigned long long other = __shfl_xor_sync(0xffffffffu, km, o);
                if (other > km) km = other;
            }
            int rsel = 63 - (int)(km & 63ull);
            float val = s_scores[b][rsel];
            acc += val * wts[k];
            if (rsel < 32) {
                if (lane == rsel) k0 = 0ull;
            } else {
                if (lane == rsel - 32) k1 = 0ull;
            }
            if (lane == 0 && write_idx) {
                out[NB * NA * NW + base * KTOP + k] = (float)rsel;
            }
        }
        if (lane == 0) out[base] = acc;
    }
}

extern "C" void kernel_launch(void* const* d_in, const int* in_sizes, int n_in,
                              void* d_out, int out_size) {
    const float* mixed   = (const float*)d_in[0];   // [2, 400000]
    const float* ref     = (const float*)d_in[1];   // [3, 64, 400000]
    const float* weights = (const float*)d_in[2];   // [8, 1]
    float* out = (float*)d_out;

    dim3 grid(NW, NA, 1);
    fused_windowed_topk<<<grid, 256>>>(mixed, ref, weights, out, out_size);
}

// round 2
// speedup vs baseline: 1.1936x; 1.1936x over previous
#include <cuda_runtime.h>
#include <stdint.h>

#define SLEN  400000
#define WIN   400
#define NW    1000      // SLEN / WIN
#define NA    3
#define NR    64
#define NB    2
#define KTOP  8
#define NF4   100       // WIN / 4
#define ROWF4 (SLEN / 4)
#define NTILES (NA * NW)
#define GRID  444       // 148 SMs * 3 CTAs

__device__ __forceinline__ float warp_sum(float v) {
#pragma unroll
    for (int o = 16; o; o >>= 1) v += __shfl_xor_sync(0xffffffffu, v, o);
    return v;
}

__device__ __forceinline__ unsigned long long mk_key(float v, int r) {
    unsigned u = __float_as_uint(v);
    u = (u & 0x80000000u) ? ~u : (u | 0x80000000u);   // order-preserving map
    return (((unsigned long long)u) << 6) | (unsigned long long)(63 - r);
}

__global__ __launch_bounds__(256, 3)
void fused_windowed_topk(const float* __restrict__ mixed,
                         const float* __restrict__ ref,
                         const float* __restrict__ weights,
                         float* __restrict__ out,
                         int out_size) {
    __shared__ float4 s_m[NB][NF4];          // mixed window, both b
    __shared__ float  s_sc[2][NB][NR];       // double-buffered scores

    const int tid  = threadIdx.x;
    const int warp = tid >> 5;
    const int lane = tid & 31;

    const bool write_idx = (out_size >= NB * NA * NW * (1 + KTOP));

    int p = 0;
    for (int tile = blockIdx.x; tile < NTILES; tile += GRID, p ^= 1) {
        const int a = tile % NA;
        const int w = tile / NA;

        // ---- stage mixed window (both b) into smem: 200 float4 ----
        if (tid < NB * NF4) {
            int b = tid / NF4, j = tid % NF4;
            s_m[b][j] = __ldg((const float4*)(mixed + (size_t)b * SLEN + w * WIN) + j);
        }
        __syncthreads();   // syncA: m ready; also fences scores[p] vs topk(tile-2)

        // ---- each warp streams 8 ref rows, loads batched for MLP=8 ----
        const float4* rp =
            (const float4*)(ref + ((size_t)a * NR + warp * 8) * SLEN + (size_t)w * WIN);
        float s0[8], s1[8];
#pragma unroll
        for (int rr = 0; rr < 8; rr++) { s0[rr] = 0.f; s1[rr] = 0.f; }

#pragma unroll
        for (int t = 0; t < 3; t++) {
            const int j4 = lane + 32 * t;
            float4 rv[8];
#pragma unroll
            for (int rr = 0; rr < 8; rr++)
                rv[rr] = __ldg(rp + rr * ROWF4 + j4);
            const float4 m0 = s_m[0][j4];
            const float4 m1 = s_m[1][j4];
#pragma unroll
            for (int rr = 0; rr < 8; rr++) {
                s0[rr] += rv[rr].x * m0.x + rv[rr].y * m0.y + rv[rr].z * m0.z + rv[rr].w * m0.w;
                s1[rr] += rv[rr].x * m1.x + rv[rr].y * m1.y + rv[rr].z * m1.z + rv[rr].w * m1.w;
            }
        }
        // tail: float4 96..99 handled by lanes 0..3 (keeps per-lane sum order)
        if (lane < 4) {
            const int j4 = 96 + lane;
            const float4 m0 = s_m[0][j4];
            const float4 m1 = s_m[1][j4];
#pragma unroll
            for (int rr = 0; rr < 8; rr++) {
                float4 rv = __ldg(rp + rr * ROWF4 + j4);
                s0[rr] += rv.x * m0.x + rv.y * m0.y + rv.z * m0.z + rv.w * m0.w;
                s1[rr] += rv.x * m1.x + rv.y * m1.y + rv.z * m1.z + rv.w * m1.w;
            }
        }

#pragma unroll
        for (int rr = 0; rr < 8; rr++) {
            float t0 = warp_sum(s0[rr]);
            float t1 = warp_sum(s1[rr]);
            if (lane == 0) {
                s_sc[p][0][warp * 8 + rr] = t0 * (1.0f / WIN);
                s_sc[p][1][warp * 8 + rr] = t1 * (1.0f / WIN);
            }
        }
        __syncthreads();   // syncB: scores[p] visible to topk warps

        // ---- top-k with JAX tie-break: warps 0/1 handle b = 0/1 ----
        if (warp < NB) {
            const int b = warp;
            float v0 = s_sc[p][b][lane];
            float v1 = s_sc[p][b][lane + 32];
            unsigned long long k0 = mk_key(v0, lane);
            unsigned long long k1 = mk_key(v1, lane + 32);

            const int base = (b * NA + a) * NW + w;
            float acc = 0.f;
#pragma unroll
            for (int k = 0; k < KTOP; k++) {
                unsigned long long km = (k0 > k1) ? k0 : k1;
#pragma unroll
                for (int o = 16; o; o >>= 1) {
                    unsigned long long other = __shfl_xor_sync(0xffffffffu, km, o);
                    if (other > km) km = other;
                }
                int rsel = 63 - (int)(km & 63ull);
                float val = s_sc[p][b][rsel];
                acc += val * __ldg(weights + k);
                if (rsel < 32) {
                    if (lane == rsel) k0 = 0ull;
                } else {
                    if (lane == rsel - 32) k1 = 0ull;
                }
                if (lane == 0 && write_idx) {
                    out[NB * NA * NW + base * KTOP + k] = (float)rsel;
                }
            }
            if (lane == 0) out[base] = acc;
        }
    }
}

extern "C" void kernel_launch(void* const* d_in, const int* in_sizes, int n_in,
                              void* d_out, int out_size) {
    const float* mixed   = (const float*)d_in[0];   // [2, 400000]
    const float* ref     = (const float*)d_in[1];   // [3, 64, 400000]
    const float* weights = (const float*)d_in[2];   // [8, 1]
    float* out = (float*)d_out;

    fused_windowed_topk<<<GRID, 256>>>(mixed, ref, weights, out, out_size);
}

// round 3
// speedup vs baseline: 1.2690x; 1.0631x over previous
#include <cuda_runtime.h>
#include <stdint.h>

#define SLEN  400000
#define WIN   400
#define NW    1000      // SLEN / WIN
#define NA    3
#define NR    64
#define NB    2
#define KTOP  8
#define NF4   100       // WIN / 4
#define ROWF4 (SLEN / 4)
#define NTILES (NA * NW) // 3000
#define GRID  444        // 148 SMs * 3 CTAs
#define NT_MAX 7         // ceil(3000/444)

__device__ __forceinline__ float warp_sum(float v) {
#pragma unroll
    for (int o = 16; o; o >>= 1) v += __shfl_xor_sync(0xffffffffu, v, o);
    return v;
}

__device__ __forceinline__ unsigned long long mk_key(float v, int r) {
    unsigned u = __float_as_uint(v);
    u = (u & 0x80000000u) ? ~u : (u | 0x80000000u);   // order-preserving map
    return (((unsigned long long)u) << 6) | (unsigned long long)(63 - r);
}

__global__ __launch_bounds__(256, 3)
void fused_windowed_topk(const float* __restrict__ mixed,
                         const float* __restrict__ ref,
                         const float* __restrict__ weights,
                         float* __restrict__ out,
                         int out_size) {
    __shared__ float4 s_m[NT_MAX][NB][NF4];   // 22400 B
    __shared__ float  s_sc[NT_MAX][NB][NR];   //  3584 B

    const int tid  = threadIdx.x;
    const int warp = tid >> 5;
    const int lane = tid & 31;
    const int bid  = blockIdx.x;

    const int cnt = (NTILES - bid + GRID - 1) / GRID;   // 6 or 7 tiles

    // ---- Phase 0: stage mixed windows for all my tiles ----
    for (int v = tid; v < cnt * NB * NF4; v += 256) {
        const int i   = v / (NB * NF4);
        const int rem = v % (NB * NF4);
        const int b   = rem / NF4;
        const int j   = rem % NF4;
        const int w   = (bid + i * GRID) / NA;
        s_m[i][b][j] = __ldg((const float4*)(mixed + (size_t)b * SLEN + w * WIN) + j);
    }
    __syncthreads();

    // ---- Phase 1: stream all ref rows for all tiles, no syncs ----
    for (int i = 0; i < cnt; i++) {
        const int tile = bid + i * GRID;
        const int a = tile % NA;
        const int w = tile / NA;

        const float4* rp =
            (const float4*)(ref + ((size_t)a * NR + warp * 8) * SLEN + (size_t)w * WIN);
        float s0[8], s1[8];
#pragma unroll
        for (int rr = 0; rr < 8; rr++) { s0[rr] = 0.f; s1[rr] = 0.f; }

#pragma unroll
        for (int t = 0; t < 3; t++) {
            const int j4 = lane + 32 * t;
            float4 rv[8];
#pragma unroll
            for (int rr = 0; rr < 8; rr++)
                rv[rr] = __ldg(rp + rr * ROWF4 + j4);
            const float4 m0 = s_m[i][0][j4];
            const float4 m1 = s_m[i][1][j4];
#pragma unroll
            for (int rr = 0; rr < 8; rr++) {
                s0[rr] += rv[rr].x * m0.x + rv[rr].y * m0.y + rv[rr].z * m0.z + rv[rr].w * m0.w;
                s1[rr] += rv[rr].x * m1.x + rv[rr].y * m1.y + rv[rr].z * m1.z + rv[rr].w * m1.w;
            }
        }
        // tail: float4 96..99 on lanes 0..3 (keeps per-lane sum order identical)
        if (lane < 4) {
            const int j4 = 96 + lane;
            const float4 m0 = s_m[i][0][j4];
            const float4 m1 = s_m[i][1][j4];
#pragma unroll
            for (int rr = 0; rr < 8; rr++) {
                float4 rv = __ldg(rp + rr * ROWF4 + j4);
                s0[rr] += rv.x * m0.x + rv.y * m0.y + rv.z * m0.z + rv.w * m0.w;
                s1[rr] += rv.x * m1.x + rv.y * m1.y + rv.z * m1.z + rv.w * m1.w;
            }
        }

#pragma unroll
        for (int rr = 0; rr < 8; rr++) {
            float t0 = warp_sum(s0[rr]);
            float t1 = warp_sum(s1[rr]);
            if (lane == 0) {
                s_sc[i][0][warp * 8 + rr] = t0 * (1.0f / WIN);
                s_sc[i][1][warp * 8 + rr] = t1 * (1.0f / WIN);
            }
        }
    }
    __syncthreads();

    // ---- Phase 2: top-k tasks (cnt*NB <= 14) spread over all 8 warps ----
    const bool write_idx = (out_size >= NB * NA * NW * (1 + KTOP));

    for (int task = warp; task < cnt * NB; task += 8) {
        const int i = task >> 1;
        const int b = task & 1;
        const int tile = bid + i * GRID;
        const int a = tile % NA;
        const int w = tile / NA;

        unsigned long long k0 = mk_key(s_sc[i][b][lane], lane);
        unsigned long long k1 = mk_key(s_sc[i][b][lane + 32], lane + 32);

        const int base = (b * NA + a) * NW + w;
        float acc = 0.f;
#pragma unroll
        for (int k = 0; k < KTOP; k++) {
            unsigned long long km = (k0 > k1) ? k0 : k1;
#pragma unroll
            for (int o = 16; o; o >>= 1) {
                unsigned long long other = __shfl_xor_sync(0xffffffffu, km, o);
                if (other > km) km = other;
            }
            const int rsel = 63 - (int)(km & 63ull);
            acc += s_sc[i][b][rsel] * __ldg(weights + k);
            if (rsel < 32) {
                if (lane == rsel) k0 = 0ull;
            } else {
                if (lane == rsel - 32) k1 = 0ull;
            }
            if (lane == 0 && write_idx) {
                out[NB * NA * NW + base * KTOP + k] = (float)rsel;
            }
        }
        if (lane == 0) out[base] = acc;
    }
}

extern "C" void kernel_launch(void* const* d_in, const int* in_sizes, int n_in,
                              void* d_out, int out_size) {
    const float* mixed   = (const float*)d_in[0];   // [2, 400000]
    const float* ref     = (const float*)d_in[1];   // [3, 64, 400000]
    const float* weights = (const float*)d_in[2];   // [8, 1]
    float* out = (float*)d_out;

    fused_windowed_topk<<<GRID, 256>>>(mixed, ref, weights, out, out_size);
}